// round 15
// baseline (speedup 1.0000x reference)
#include <cuda_runtime.h>
#include <cstdint>

#define TT 1024      // timesteps
#define DD 1024      // model dim
#define A3 3072      // 3 * attention_dim
#define FF 4096      // feedforward dim
#define BT 2048      // B * T rows
#define NBH 32       // B * H batched heads

// ---------------- scratch (device globals; no allocations allowed) ----------------
__device__ float g_qkv_u[BT * A3];
__device__ float g_qkv_v[BT * A3];
__device__ float g_G[NBH * 4096];
__device__ float g_H[NBH * 4096];
__device__ float g_Gpart[8 * NBH * 4096];
__device__ float g_qp[BT * DD];
__device__ float g_comb[(size_t)NBH * TT * TT];
__device__ float g_attn[BT * DD];
__device__ float g_proj[BT * DD];
__device__ float g_o1[BT * DD];
__device__ float g_ffn[BT * FF];
__device__ float g_f2[BT * DD];
// tf32-rounded copies (PREC=1 operands)
__device__ float g_Wo_r[DD * DD];
__device__ float g_W1_r[DD * FF];
__device__ float g_W2_r[FF * DD];
__device__ float g_WuV_r[DD * DD];
__device__ float g_WvV_r[DD * DD];
// hi/lo pre-split operands (PREC=2 GEMMs)
__device__ float g_src_hi[BT * DD],  g_src_lo[BT * DD];
__device__ float g_aux_hi[BT * DD],  g_aux_lo[BT * DD];
__device__ float g_WuQK_hi[DD * 2048], g_WuQK_lo[DD * 2048];
__device__ float g_WvQK_hi[DD * 2048], g_WvQK_lo[DD * 2048];
__device__ float g_kc_hi[2 * BT * 1024], g_kc_lo[2 * BT * 1024];
__device__ float g_qp_hi[BT * DD], g_qp_lo[BT * DD];

// xor-swizzled smem offset: row k (16 rows), m within row of width W.
#define SWZ(k, m, W) (((k) * (W)) + ((m) ^ (((((k) & 3) ^ (((k) >> 2) & 3))) << 3)))

__device__ __forceinline__ float f2tf32f(float x) {
    unsigned r;
    asm("cvt.rna.tf32.f32 %0, %1;" : "=r"(r) : "f"(x));
    return __uint_as_float(r);
}

#define MMA_TF32(d, a, b)                                                      \
    asm volatile(                                                              \
        "mma.sync.aligned.m16n8k8.row.col.f32.tf32.tf32.f32 "                  \
        "{%0,%1,%2,%3},{%4,%5,%6,%7},{%8,%9},{%0,%1,%2,%3};"                   \
        : "+f"((d)[0]), "+f"((d)[1]), "+f"((d)[2]), "+f"((d)[3])               \
        : "r"((a)[0]), "r"((a)[1]), "r"((a)[2]), "r"((a)[3]),                  \
          "r"((b)[0]), "r"((b)[1]))

#define CP_ASYNC16(dst, src)                                                   \
    asm volatile("cp.async.cg.shared.global [%0], [%1], 16;" :: "r"(dst), "l"(src))
#define CP_COMMIT() asm volatile("cp.async.commit_group;")
#define CP_WAIT(n)  asm volatile("cp.async.wait_group %0;" :: "n"(n))

// ---------------------------------------------------------------------------------
// Tensor-core GEMM: C[M x N] = A[M x K] * B (+bias, relu, scale, col-mask)
// PREC 1: tf32, cp.async 4-stage pipeline (operands pre-rounded by producers)
// PREC 2: 3xTF32, cp.async 4-stage pipeline on pre-split hi/lo gmem operands
// PREC 3: 3xTF32, cvt-at-store double buffer (for small/strided cases)
// hilo epilogue: 1 = write hi/lo decomposition of C (full range, ld=ldc)
//                2 = write hi/lo of cols >= 1024 to Chi/Clo with ld=1024
// ---------------------------------------------------------------------------------
template <int BN, int PREC>
__global__ void __launch_bounds__(256) mma_gemm(
    const float* __restrict__ A, const float* __restrict__ Alo2,
    int lda, long long sAb, long long sAh,
    const float* __restrict__ B, const float* __restrict__ Blo2,
    int ldb, long long sBb, long long sBh, int transB,
    float* __restrict__ C, int ldc, long long sCb, long long sCh,
    float* __restrict__ Chi, float* __restrict__ Clo, int hilo,
    int K, const float* __restrict__ bias, int relu, float scale,
    const int* __restrict__ mask, int round_out)
{
    constexpr int NF = BN / 16;
    constexpr int BF4 = (BN * 16 / 4) / 256;
    constexpr int NH = (NF > 4) ? 2 : 1;
    constexpr int NFH = NF / NH;

    extern __shared__ float sm[];

    int z = blockIdx.z, b = z >> 4, h = z & 15;
    A += (size_t)b * sAb + (size_t)h * sAh;
    if (Alo2) Alo2 += (size_t)b * sAb + (size_t)h * sAh;
    B += (size_t)b * sBb + (size_t)h * sBh;
    if (Blo2) Blo2 += (size_t)b * sBb + (size_t)h * sBh;
    C += (size_t)b * sCb + (size_t)h * sCh;
    if (hilo) { Chi += (size_t)b * sCb + (size_t)h * sCh;
                Clo += (size_t)b * sCb + (size_t)h * sCh; }
    const int* mrow = mask ? (mask + b * TT) : (const int*)0;

    int tid = threadIdx.x, lane = tid & 31, warp = tid >> 5;
    int wy = warp >> 1, wx = warp & 1;
    int wm = wy * 32, wn = wx * (BN / 2);
    int g = lane >> 2, q = lane & 3;
    int m0 = blockIdx.y * 128, n0 = blockIdx.x * BN;

    float acc[2][NF][4];
    #pragma unroll
    for (int mi = 0; mi < 2; mi++)
        #pragma unroll
        for (int nj = 0; nj < NF; nj++)
            #pragma unroll
            for (int e = 0; e < 4; e++) acc[mi][nj][e] = 0.f;

    if constexpr (PREC == 1) {
        constexpr int STAGES = 4;
        constexpr int AW = 16 * 128;
        constexpr int BW = 16 * BN;
        float* Af = sm;
        float* Bf = sm + STAGES * AW;
        unsigned aBase = (unsigned)__cvta_generic_to_shared(Af);
        unsigned bBase = (unsigned)__cvta_generic_to_shared(Bf);

        auto issue = [&](int slab, int stg) {
            #pragma unroll
            for (int i = 0; i < 2; i++) {
                int id = tid + 256 * i;
                int m = id >> 2, c = id & 3;
                const float* src = A + (size_t)(m0 + m) * lda + slab * 16 + c * 4;
                unsigned dst = aBase + (unsigned)(stg * AW + m * 16 + ((c ^ (m & 3)) << 2)) * 4u;
                CP_ASYNC16(dst, src);
            }
            #pragma unroll
            for (int i = 0; i < BF4; i++) {
                int id = tid + 256 * i;
                int kr = id / (BN / 4), nc4 = (id % (BN / 4)) * 4;
                const float* src = B + (size_t)(slab * 16 + kr) * ldb + n0 + nc4;
                int sw = (((kr & 3) ^ ((kr >> 2) & 3)) << 3);
                unsigned dst = bBase + (unsigned)(stg * BW + kr * BN + (nc4 ^ sw)) * 4u;
                CP_ASYNC16(dst, src);
            }
            CP_COMMIT();
        };

        int nslab = K / 16;
        #pragma unroll
        for (int s = 0; s < STAGES - 1; s++) issue(s, s);

        for (int s = 0; s < nslab; s++) {
            CP_WAIT(STAGES - 2);
            __syncthreads();
            int stg = s & 3;
            const float* pa = Af + stg * AW;
            const float* pb = Bf + stg * BW;

            #pragma unroll
            for (int kk = 0; kk < 16; kk += 8) {
                unsigned ah[2][4];
                #pragma unroll
                for (int mi = 0; mi < 2; mi++)
                    #pragma unroll
                    for (int e = 0; e < 4; e++) {
                        int m = wm + mi * 16 + g + ((e & 1) ? 8 : 0);
                        int c = (kk >> 2) + ((e >= 2) ? 1 : 0);
                        ah[mi][e] = __float_as_uint(pa[m * 16 + q + ((c ^ (m & 3)) << 2)]);
                    }
                #pragma unroll
                for (int hh = 0; hh < NH; hh++) {
                    unsigned bh[NFH][2];
                    #pragma unroll
                    for (int j = 0; j < NFH; j++) {
                        int n = wn + (hh * NFH + j) * 8 + g;
                        bh[j][0] = __float_as_uint(pb[SWZ(kk + q, n, BN)]);
                        bh[j][1] = __float_as_uint(pb[SWZ(kk + q + 4, n, BN)]);
                    }
                    #pragma unroll
                    for (int mi = 0; mi < 2; mi++)
                        #pragma unroll
                        for (int j = 0; j < NFH; j++)
                            MMA_TF32(acc[mi][hh * NFH + j], ah[mi], bh[j]);
                }
            }

            int nxt = s + STAGES - 1;
            if (nxt < nslab) issue(nxt, nxt & 3);
            else CP_COMMIT();
        }
    } else if constexpr (PREC == 2) {
        // -------- 3xTF32 via cp.async pipeline on pre-split hi/lo operands --------
        constexpr int STAGES = 4;
        constexpr int AW = 16 * 128;
        constexpr int BW = 16 * BN;
        float* Ah_s = sm;
        float* Al_s = sm + STAGES * AW;
        float* Bh_s = sm + 2 * STAGES * AW;
        float* Bl_s = sm + 2 * STAGES * AW + STAGES * BW;
        unsigned ahB = (unsigned)__cvta_generic_to_shared(Ah_s);
        unsigned alB = (unsigned)__cvta_generic_to_shared(Al_s);
        unsigned bhB = (unsigned)__cvta_generic_to_shared(Bh_s);
        unsigned blB = (unsigned)__cvta_generic_to_shared(Bl_s);

        auto issue = [&](int slab, int stg) {
            #pragma unroll
            for (int i = 0; i < 2; i++) {
                int id = tid + 256 * i;
                int m = id >> 2, c = id & 3;
                size_t goff = (size_t)(m0 + m) * lda + slab * 16 + c * 4;
                unsigned soff = (unsigned)(stg * AW + m * 16 + ((c ^ (m & 3)) << 2)) * 4u;
                CP_ASYNC16(ahB + soff, A + goff);
                CP_ASYNC16(alB + soff, Alo2 + goff);
            }
            if (!transB) {
                #pragma unroll
                for (int i = 0; i < BF4; i++) {
                    int id = tid + 256 * i;
                    int kr = id / (BN / 4), nc4 = (id % (BN / 4)) * 4;
                    size_t goff = (size_t)(slab * 16 + kr) * ldb + n0 + nc4;
                    int sw = (((kr & 3) ^ ((kr >> 2) & 3)) << 3);
                    unsigned soff = (unsigned)(stg * BW + kr * BN + (nc4 ^ sw)) * 4u;
                    CP_ASYNC16(bhB + soff, B + goff);
                    CP_ASYNC16(blB + soff, Blo2 + goff);
                }
            } else {
                #pragma unroll
                for (int i = 0; i < BF4; i++) {
                    int id = tid + 256 * i;
                    int n = id >> 2, c = id & 3;
                    size_t goff = (size_t)(n0 + n) * ldb + slab * 16 + c * 4;
                    unsigned soff = (unsigned)(stg * BW + n * 16 + ((c ^ (n & 3)) << 2)) * 4u;
                    CP_ASYNC16(bhB + soff, B + goff);
                    CP_ASYNC16(blB + soff, Blo2 + goff);
                }
            }
            CP_COMMIT();
        };

        int nslab = K / 16;
        #pragma unroll
        for (int s = 0; s < STAGES - 1; s++) issue(s, s);

        for (int s = 0; s < nslab; s++) {
            CP_WAIT(STAGES - 2);
            __syncthreads();
            int stg = s & 3;
            const float* pah = Ah_s + stg * AW;
            const float* pal = Al_s + stg * AW;
            const float* pbh = Bh_s + stg * BW;
            const float* pbl = Bl_s + stg * BW;

            #pragma unroll
            for (int kk = 0; kk < 16; kk += 8) {
                unsigned ah[2][4], al[2][4];
                #pragma unroll
                for (int mi = 0; mi < 2; mi++)
                    #pragma unroll
                    for (int e = 0; e < 4; e++) {
                        int m = wm + mi * 16 + g + ((e & 1) ? 8 : 0);
                        int c = (kk >> 2) + ((e >= 2) ? 1 : 0);
                        int idx = m * 16 + q + ((c ^ (m & 3)) << 2);
                        ah[mi][e] = __float_as_uint(pah[idx]);
                        al[mi][e] = __float_as_uint(pal[idx]);
                    }
                #pragma unroll
                for (int hh = 0; hh < NH; hh++) {
                    unsigned bh[NFH][2], bl[NFH][2];
                    #pragma unroll
                    for (int j = 0; j < NFH; j++) {
                        int n = wn + (hh * NFH + j) * 8 + g;
                        if (!transB) {
                            bh[j][0] = __float_as_uint(pbh[SWZ(kk + q, n, BN)]);
                            bh[j][1] = __float_as_uint(pbh[SWZ(kk + q + 4, n, BN)]);
                            bl[j][0] = __float_as_uint(pbl[SWZ(kk + q, n, BN)]);
                            bl[j][1] = __float_as_uint(pbl[SWZ(kk + q + 4, n, BN)]);
                        } else {
                            int c1 = kk >> 2;
                            int base = n * 16 + q;
                            bh[j][0] = __float_as_uint(pbh[base + ((c1 ^ (n & 3)) << 2)]);
                            bh[j][1] = __float_as_uint(pbh[base + (((c1 + 1) ^ (n & 3)) << 2)]);
                            bl[j][0] = __float_as_uint(pbl[base + ((c1 ^ (n & 3)) << 2)]);
                            bl[j][1] = __float_as_uint(pbl[base + (((c1 + 1) ^ (n & 3)) << 2)]);
                        }
                    }
                    #pragma unroll
                    for (int mi = 0; mi < 2; mi++)
                        #pragma unroll
                        for (int j = 0; j < NFH; j++) {
                            int nj = hh * NFH + j;
                            MMA_TF32(acc[mi][nj], ah[mi], bh[j]);
                            MMA_TF32(acc[mi][nj], ah[mi], bl[j]);
                            MMA_TF32(acc[mi][nj], al[mi], bh[j]);
                        }
                }
            }

            int nxt = s + STAGES - 1;
            if (nxt < nslab) issue(nxt, nxt & 3);
            else CP_COMMIT();
        }
    } else {
        // -------- PREC==3: cvt-at-store hi/lo double buffer (small/strided cases) --
        constexpr int CC = 2;
        constexpr int AE = 16 * 128;
        constexpr int BE = 16 * BN;
        float* Asm = sm;
        float* Bsm = sm + 2 * CC * AE;

        float4 va[2];
        float4 vb[BF4];

        auto loadA = [&](int k0) {
            #pragma unroll
            for (int i = 0; i < 2; i++) {
                int id = tid + 256 * i;
                int r = id >> 2, c4 = (id & 3) * 4;
                va[i] = *(const float4*)&A[(size_t)(m0 + r) * lda + k0 + c4];
            }
        };
        auto storeA = [&](int bf) {
            float* p = Asm + bf * CC * AE;
            #pragma unroll
            for (int i = 0; i < 2; i++) {
                int id = tid + 256 * i;
                int r = id >> 2, c4 = (id & 3) * 4;
                float xs[4] = {va[i].x, va[i].y, va[i].z, va[i].w};
                #pragma unroll
                for (int s = 0; s < 4; s++) {
                    float hi = f2tf32f(xs[s]);
                    p[SWZ(c4 + s, r, 128)] = hi;
                    p[AE + SWZ(c4 + s, r, 128)] = f2tf32f(xs[s] - hi);
                }
            }
        };
        auto loadB = [&](int k0) {
            if (!transB) {
                #pragma unroll
                for (int i = 0; i < BF4; i++) {
                    int id = tid + 256 * i;
                    int kr = id / (BN / 4), nc4 = (id % (BN / 4)) * 4;
                    vb[i] = *(const float4*)&B[(size_t)(k0 + kr) * ldb + n0 + nc4];
                }
            } else {
                #pragma unroll
                for (int i = 0; i < BF4; i++) {
                    int id = tid + 256 * i;
                    int n = id >> 2, c4 = (id & 3) * 4;
                    vb[i] = *(const float4*)&B[(size_t)(n0 + n) * ldb + k0 + c4];
                }
            }
        };
        auto storeB = [&](int bf) {
            float* p = Bsm + bf * CC * BE;
            if (!transB) {
                #pragma unroll
                for (int i = 0; i < BF4; i++) {
                    int id = tid + 256 * i;
                    int kr = id / (BN / 4), nc4 = (id % (BN / 4)) * 4;
                    int sw = (((kr & 3) ^ ((kr >> 2) & 3)) << 3);
                    float xs[4] = {vb[i].x, vb[i].y, vb[i].z, vb[i].w};
                    float4 hv, lv;
                    hv.x = f2tf32f(xs[0]); hv.y = f2tf32f(xs[1]);
                    hv.z = f2tf32f(xs[2]); hv.w = f2tf32f(xs[3]);
                    *(float4*)&p[kr * BN + (nc4 ^ sw)] = hv;
                    lv.x = f2tf32f(xs[0] - hv.x); lv.y = f2tf32f(xs[1] - hv.y);
                    lv.z = f2tf32f(xs[2] - hv.z); lv.w = f2tf32f(xs[3] - hv.w);
                    *(float4*)&p[BE + kr * BN + (nc4 ^ sw)] = lv;
                }
            } else {
                #pragma unroll
                for (int i = 0; i < BF4; i++) {
                    int id = tid + 256 * i;
                    int n = id >> 2, c4 = (id & 3) * 4;
                    float xs[4] = {vb[i].x, vb[i].y, vb[i].z, vb[i].w};
                    #pragma unroll
                    for (int s = 0; s < 4; s++) {
                        float hi = f2tf32f(xs[s]);
                        p[SWZ(c4 + s, n, BN)] = hi;
                        p[BE + SWZ(c4 + s, n, BN)] = f2tf32f(xs[s] - hi);
                    }
                }
            }
        };

        loadA(0); loadB(0);
        storeA(0); storeB(0);
        __syncthreads();

        int buf = 0;
        for (int k0 = 0; k0 < K; k0 += 16) {
            bool more = (k0 + 16) < K;
            if (more) { loadA(k0 + 16); loadB(k0 + 16); }

            const float* pa = Asm + buf * CC * AE;
            const float* pb = Bsm + buf * CC * BE;

            #pragma unroll
            for (int kk = 0; kk < 16; kk += 8) {
                unsigned ah[2][4], al[2][4];
                #pragma unroll
                for (int mi = 0; mi < 2; mi++)
                    #pragma unroll
                    for (int e = 0; e < 4; e++) {
                        int kq = kk + q + ((e >= 2) ? 4 : 0);
                        int m = wm + mi * 16 + g + ((e & 1) ? 8 : 0);
                        ah[mi][e] = __float_as_uint(pa[SWZ(kq, m, 128)]);
                        al[mi][e] = __float_as_uint(pa[AE + SWZ(kq, m, 128)]);
                    }
                #pragma unroll
                for (int hh = 0; hh < NH; hh++) {
                    unsigned bh[NFH][2], bl[NFH][2];
                    #pragma unroll
                    for (int j = 0; j < NFH; j++) {
                        int n = wn + (hh * NFH + j) * 8 + g;
                        bh[j][0] = __float_as_uint(pb[SWZ(kk + q, n, BN)]);
                        bh[j][1] = __float_as_uint(pb[SWZ(kk + q + 4, n, BN)]);
                        bl[j][0] = __float_as_uint(pb[BE + SWZ(kk + q, n, BN)]);
                        bl[j][1] = __float_as_uint(pb[BE + SWZ(kk + q + 4, n, BN)]);
                    }
                    #pragma unroll
                    for (int mi = 0; mi < 2; mi++)
                        #pragma unroll
                        for (int j = 0; j < NFH; j++) {
                            int nj = hh * NFH + j;
                            MMA_TF32(acc[mi][nj], ah[mi], bh[j]);
                            MMA_TF32(acc[mi][nj], ah[mi], bl[j]);
                            MMA_TF32(acc[mi][nj], al[mi], bh[j]);
                        }
                }
            }

            if (more) {
                storeA(buf ^ 1); storeB(buf ^ 1);
                buf ^= 1;
                __syncthreads();
            }
        }
    }

    // epilogue
    #pragma unroll
    for (int mi = 0; mi < 2; mi++)
        #pragma unroll
        for (int r2 = 0; r2 < 2; r2++) {
            int row = m0 + wm + mi * 16 + g + r2 * 8;
            #pragma unroll
            for (int nj = 0; nj < NF; nj++) {
                int col = n0 + wn + nj * 8 + 2 * q;
                float v0 = acc[mi][nj][r2 * 2 + 0] * scale;
                float v1 = acc[mi][nj][r2 * 2 + 1] * scale;
                if (bias) { v0 += bias[col]; v1 += bias[col + 1]; }
                if (mrow) {
                    if (!mrow[col]) v0 = 0.f;
                    if (!mrow[col + 1]) v1 = 0.f;
                }
                if (relu) { v0 = fmaxf(v0, 0.f); v1 = fmaxf(v1, 0.f); }
                if (round_out) { v0 = f2tf32f(v0); v1 = f2tf32f(v1); }
                if (hilo == 1 || (hilo == 2 && col >= 1024)) {
                    long long hrow = (long long)row * ((hilo == 2) ? 1024 : ldc);
                    int hc = (hilo == 2) ? col - 1024 : col;
                    float h0 = f2tf32f(v0), h1 = f2tf32f(v1);
                    Chi[hrow + hc] = h0; Chi[hrow + hc + 1] = h1;
                    Clo[hrow + hc] = f2tf32f(v0 - h0);
                    Clo[hrow + hc + 1] = f2tf32f(v1 - h1);
                }
                float2 o; o.x = v0; o.y = v1;
                *(float2*)&C[(size_t)row * ldc + col] = o;
            }
        }
}

// -------- producer-side kernels: tf32 round / hi-lo split -------------------------
__global__ void __launch_bounds__(256) tf32_round_kernel(
    const float* __restrict__ in, float* __restrict__ out, int n4)
{
    int i = blockIdx.x * 256 + threadIdx.x;
    if (i < n4) {
        float4 v = ((const float4*)in)[i];
        v.x = f2tf32f(v.x); v.y = f2tf32f(v.y); v.z = f2tf32f(v.z); v.w = f2tf32f(v.w);
        ((float4*)out)[i] = v;
    }
}

__global__ void __launch_bounds__(256) tf32_round_strided(
    const float* __restrict__ in, float* __restrict__ out, int ld_in)
{
    int r = blockIdx.y;
    int c = threadIdx.x * 4;
    float4 v = *(const float4*)(in + (size_t)r * ld_in + c);
    v.x = f2tf32f(v.x); v.y = f2tf32f(v.y); v.z = f2tf32f(v.z); v.w = f2tf32f(v.w);
    *(float4*)(out + (size_t)r * 1024 + c) = v;
}

__global__ void __launch_bounds__(256) split_kernel(
    const float* __restrict__ in, float* __restrict__ hi, float* __restrict__ lo, int n4)
{
    int i = blockIdx.x * 256 + threadIdx.x;
    if (i < n4) {
        float4 v = ((const float4*)in)[i];
        float4 hv, lv;
        hv.x = f2tf32f(v.x); lv.x = f2tf32f(v.x - hv.x);
        hv.y = f2tf32f(v.y); lv.y = f2tf32f(v.y - hv.y);
        hv.z = f2tf32f(v.z); lv.z = f2tf32f(v.z - hv.z);
        hv.w = f2tf32f(v.w); lv.w = f2tf32f(v.w - hv.w);
        ((float4*)hi)[i] = hv;
        ((float4*)lo)[i] = lv;
    }
}

// cols 0..2047 of a [1024][3072] matrix -> [1024][2048] hi/lo. grid (2, 1024)
__global__ void __launch_bounds__(256) split_cols_kernel(
    const float* __restrict__ in, float* __restrict__ hi, float* __restrict__ lo)
{
    int r = blockIdx.y;
    int c = (blockIdx.x * 256 + threadIdx.x) * 4;
    float4 v = *(const float4*)(in + (size_t)r * A3 + c);
    float4 hv, lv;
    hv.x = f2tf32f(v.x); lv.x = f2tf32f(v.x - hv.x);
    hv.y = f2tf32f(v.y); lv.y = f2tf32f(v.y - hv.y);
    hv.z = f2tf32f(v.z); lv.z = f2tf32f(v.z - hv.z);
    hv.w = f2tf32f(v.w); lv.w = f2tf32f(v.w - hv.w);
    *(float4*)(hi + (size_t)r * 2048 + c) = hv;
    *(float4*)(lo + (size_t)r * 2048 + c) = lv;
}

// -------- split-K G partials: G = K^T diag(mask) Q per (b,h). grid (32, 8) -------
__global__ void __launch_bounds__(256) gmat_part(
    const float* __restrict__ qkv, const int* __restrict__ mask, float* __restrict__ part)
{
    int z = blockIdx.x; int b = z >> 4; int h = z & 15;
    int tb = blockIdx.y * 128;
    const float* Kb = qkv + (size_t)b * TT * A3 + 1024 + h * 64;
    const float* Qb = qkv + (size_t)b * TT * A3 + h * 64;
    __shared__ float Ks[64][65];
    __shared__ float Qs[64][65];
    int tid = threadIdx.x, tx = tid & 15, ty = tid >> 4;
    float acc[4][4] = {};

    for (int t0 = tb; t0 < tb + 128; t0 += 64) {
        #pragma unroll
        for (int l = 0; l < 4; l++) {
            int lin = tid + l * 256; int r = lin >> 4; int c4 = (lin & 15) * 4;
            int trow = t0 + r;
            float mk = mask[b * TT + trow] ? 1.0f : 0.0f;
            float4 kv = *(const float4*)&Kb[(size_t)trow * A3 + c4];
            Ks[r][c4] = kv.x * mk; Ks[r][c4 + 1] = kv.y * mk;
            Ks[r][c4 + 2] = kv.z * mk; Ks[r][c4 + 3] = kv.w * mk;
            float4 qv = *(const float4*)&Qb[(size_t)trow * A3 + c4];
            Qs[r][c4] = qv.x; Qs[r][c4 + 1] = qv.y; Qs[r][c4 + 2] = qv.z; Qs[r][c4 + 3] = qv.w;
        }
        __syncthreads();
        #pragma unroll
        for (int t = 0; t < 64; t++) {
            float ra[4], rb[4];
            #pragma unroll
            for (int i = 0; i < 4; i++) ra[i] = Ks[t][ty * 4 + i];
            #pragma unroll
            for (int j = 0; j < 4; j++) rb[j] = Qs[t][tx * 4 + j];
            #pragma unroll
            for (int i = 0; i < 4; i++)
                #pragma unroll
                for (int j = 0; j < 4; j++) acc[i][j] = fmaf(ra[i], rb[j], acc[i][j]);
        }
        __syncthreads();
    }
    float* P = part + ((size_t)blockIdx.y * NBH + z) * 4096;
    #pragma unroll
    for (int i = 0; i < 4; i++) {
        float4 o; o.x = acc[i][0]; o.y = acc[i][1]; o.z = acc[i][2]; o.w = acc[i][3];
        *(float4*)&P[(ty * 4 + i) * 64 + tx * 4] = o;
    }
}

__global__ void __launch_bounds__(256) gmat_reduce(
    const float* __restrict__ part, float* __restrict__ G)
{
    int z = blockIdx.x;
    int e = blockIdx.y * 512 + threadIdx.x;
    #pragma unroll
    for (int i = 0; i < 2; i++, e += 256) {
        float s = 0.f;
        #pragma unroll
        for (int k = 0; k < 8; k++) s += part[((size_t)k * NBH + z) * 4096 + e];
        G[(size_t)z * 4096 + e] = s;
    }
}

// -------- row softmax over 1024 cols, in place; output tf32-rounded --------------
__global__ void __launch_bounds__(256) softmax_kernel(float* __restrict__ data)
{
    __shared__ float red[8];
    size_t row = blockIdx.x;
    float4* p = (float4*)(data + row * TT);
    int tid = threadIdx.x;
    float4 v = p[tid];
    float m = fmaxf(fmaxf(v.x, v.y), fmaxf(v.z, v.w));
    #pragma unroll
    for (int o = 16; o; o >>= 1) m = fmaxf(m, __shfl_xor_sync(0xffffffffu, m, o));
    if ((tid & 31) == 0) red[tid >> 5] = m;
    __syncthreads();
    m = red[0];
    #pragma unroll
    for (int i = 1; i < 8; i++) m = fmaxf(m, red[i]);
    v.x = expf(v.x - m); v.y = expf(v.y - m); v.z = expf(v.z - m); v.w = expf(v.w - m);
    float s = v.x + v.y + v.z + v.w;
    #pragma unroll
    for (int o = 16; o; o >>= 1) s += __shfl_xor_sync(0xffffffffu, s, o);
    __syncthreads();
    if ((tid & 31) == 0) red[tid >> 5] = s;
    __syncthreads();
    s = red[0] + red[1] + red[2] + red[3] + red[4] + red[5] + red[6] + red[7];
    float inv = 1.0f / s;
    v.x = f2tf32f(v.x * inv); v.y = f2tf32f(v.y * inv);
    v.z = f2tf32f(v.z * inv); v.w = f2tf32f(v.w * inv);
    p[tid] = v;
}

// -------- out = LayerNorm(x + y) * g + b (optionally tf32-rounded) ---------------
__global__ void __launch_bounds__(256) add_ln_kernel(
    const float* __restrict__ x, const float* __restrict__ y,
    const float* __restrict__ g, const float* __restrict__ beta,
    float* __restrict__ out, int round_out)
{
    __shared__ float s1[8], s2[8];
    size_t row = blockIdx.x;
    int tid = threadIdx.x;
    float4 xv = ((const float4*)(x + row * DD))[tid];
    float4 yv = ((const float4*)(y + row * DD))[tid];
    float4 v;
    v.x = xv.x + yv.x; v.y = xv.y + yv.y; v.z = xv.z + yv.z; v.w = xv.w + yv.w;
    float s = v.x + v.y + v.z + v.w;
    float q = v.x * v.x + v.y * v.y + v.z * v.z + v.w * v.w;
    #pragma unroll
    for (int o = 16; o; o >>= 1) {
        s += __shfl_xor_sync(0xffffffffu, s, o);
        q += __shfl_xor_sync(0xffffffffu, q, o);
    }
    if ((tid & 31) == 0) { s1[tid >> 5] = s; s2[tid >> 5] = q; }
    __syncthreads();
    s = s1[0] + s1[1] + s1[2] + s1[3] + s1[4] + s1[5] + s1[6] + s1[7];
    q = s2[0] + s2[1] + s2[2] + s2[3] + s2[4] + s2[5] + s2[6] + s2[7];
    float mean = s * (1.0f / 1024.0f);
    float var = q * (1.0f / 1024.0f) - mean * mean;
    float r = rsqrtf(var + 1e-5f);
    float4 gv = ((const float4*)g)[tid];
    float4 bv = ((const float4*)beta)[tid];
    float4 o;
    o.x = (v.x - mean) * r * gv.x + bv.x;
    o.y = (v.y - mean) * r * gv.y + bv.y;
    o.z = (v.z - mean) * r * gv.z + bv.z;
    o.w = (v.w - mean) * r * gv.w + bv.w;
    if (round_out) {
        o.x = f2tf32f(o.x); o.y = f2tf32f(o.y);
        o.z = f2tf32f(o.z); o.w = f2tf32f(o.w);
    }
    ((float4*)(out + row * DD))[tid] = o;
}

// ----------------------------------- host ----------------------------------------
static inline int smem_bytes(int BN, int PREC) {
    if (PREC == 1) return 4 * (16 * 128 + 16 * BN) * 4;          // 4-stage cp.async
    if (PREC == 2) return 4 * (16 * 128 + 16 * BN) * 2 * 4;      // 4-stage hi/lo
    return (2 * 2 * 16 * 128 + 2 * 2 * 16 * BN) * 4;             // PREC=3 double buffer
}

extern "C" void kernel_launch(void* const* d_in, const int* in_sizes, int n_in,
                              void* d_out, int out_size)
{
    const float* src = (const float*)d_in[0];
    const float* aux = (const float*)d_in[1];
    const float* Wu  = (const float*)d_in[2];
    const float* bu  = (const float*)d_in[3];
    const float* Wv  = (const float*)d_in[4];
    const float* bv  = (const float*)d_in[5];
    const float* Wo  = (const float*)d_in[6];
    const float* bo  = (const float*)d_in[7];
    const float* W1  = (const float*)d_in[8];
    const float* b1  = (const float*)d_in[9];
    const float* W2  = (const float*)d_in[10];
    const float* b2  = (const float*)d_in[11];
    const float* g1  = (const float*)d_in[12];
    const float* be1 = (const float*)d_in[13];
    const float* g2  = (const float*)d_in[14];
    const float* be2 = (const float*)d_in[15];
    const int* src_mask = (const int*)d_in[16];
    const int* aux_mask = (const int*)d_in[17];

    float *qkv_u, *qkv_v, *Gb, *Hb, *Gpart, *qp, *comb, *attn, *proj, *o1, *ffn, *f2;
    float *Wo_r, *W1_r, *W2_r, *WuV_r, *WvV_r;
    float *src_hi, *src_lo, *aux_hi, *aux_lo;
    float *WuQK_hi, *WuQK_lo, *WvQK_hi, *WvQK_lo;
    float *kc_hi, *kc_lo, *qp_hi, *qp_lo;
    cudaGetSymbolAddress((void**)&qkv_u, g_qkv_u);
    cudaGetSymbolAddress((void**)&qkv_v, g_qkv_v);
    cudaGetSymbolAddress((void**)&Gb, g_G);
    cudaGetSymbolAddress((void**)&Hb, g_H);
    cudaGetSymbolAddress((void**)&Gpart, g_Gpart);
    cudaGetSymbolAddress((void**)&qp, g_qp);
    cudaGetSymbolAddress((void**)&comb, g_comb);
    cudaGetSymbolAddress((void**)&attn, g_attn);
    cudaGetSymbolAddress((void**)&proj, g_proj);
    cudaGetSymbolAddress((void**)&o1, g_o1);
    cudaGetSymbolAddress((void**)&ffn, g_ffn);
    cudaGetSymbolAddress((void**)&f2, g_f2);
    cudaGetSymbolAddress((void**)&Wo_r, g_Wo_r);
    cudaGetSymbolAddress((void**)&W1_r, g_W1_r);
    cudaGetSymbolAddress((void**)&W2_r, g_W2_r);
    cudaGetSymbolAddress((void**)&WuV_r, g_WuV_r);
    cudaGetSymbolAddress((void**)&WvV_r, g_WvV_r);
    cudaGetSymbolAddress((void**)&src_hi, g_src_hi);
    cudaGetSymbolAddress((void**)&src_lo, g_src_lo);
    cudaGetSymbolAddress((void**)&aux_hi, g_aux_hi);
    cudaGetSymbolAddress((void**)&aux_lo, g_aux_lo);
    cudaGetSymbolAddress((void**)&WuQK_hi, g_WuQK_hi);
    cudaGetSymbolAddress((void**)&WuQK_lo, g_WuQK_lo);
    cudaGetSymbolAddress((void**)&WvQK_hi, g_WvQK_hi);
    cudaGetSymbolAddress((void**)&WvQK_lo, g_WvQK_lo);
    cudaGetSymbolAddress((void**)&kc_hi, g_kc_hi);
    cudaGetSymbolAddress((void**)&kc_lo, g_kc_lo);
    cudaGetSymbolAddress((void**)&qp_hi, g_qp_hi);
    cudaGetSymbolAddress((void**)&qp_lo, g_qp_lo);

    // raise dynamic-smem caps — unconditional (idempotent host-side config)
    cudaFuncSetAttribute(mma_gemm<128, 2>, cudaFuncAttributeMaxDynamicSharedMemorySize, smem_bytes(128, 2));
    cudaFuncSetAttribute(mma_gemm<128, 1>, cudaFuncAttributeMaxDynamicSharedMemorySize, smem_bytes(128, 1));
    cudaFuncSetAttribute(mma_gemm<64, 3>,  cudaFuncAttributeMaxDynamicSharedMemorySize, smem_bytes(64, 3));
    cudaFuncSetAttribute(mma_gemm<64, 1>,  cudaFuncAttributeMaxDynamicSharedMemorySize, smem_bytes(64, 1));

    const float inv64 = 1.0f / 64.0f;
    const long long Z = 0;
    const int S128_2 = smem_bytes(128, 2), S128_1 = smem_bytes(128, 1);
    const int S64_3 = smem_bytes(64, 3),   S64_1 = smem_bytes(64, 1);
    const float* FNUL = (const float*)0;
    float* MNUL = (float*)0;
    const int* INUL = (const int*)0;

    // producer-side prep: hi/lo splits + tf32 rounds
    split_kernel<<<2048, 256>>>(src, src_hi, src_lo, BT * DD / 4);
    split_kernel<<<2048, 256>>>(aux, aux_hi, aux_lo, BT * DD / 4);
    split_cols_kernel<<<dim3(2, 1024), 256>>>(Wu, WuQK_hi, WuQK_lo);
    split_cols_kernel<<<dim3(2, 1024), 256>>>(Wv, WvQK_hi, WvQK_lo);
    tf32_round_kernel<<<(DD * DD / 4 + 255) / 256, 256>>>(Wo, Wo_r, DD * DD / 4);
    tf32_round_kernel<<<(DD * FF / 4 + 255) / 256, 256>>>(W1, W1_r, DD * FF / 4);
    tf32_round_kernel<<<(FF * DD / 4 + 255) / 256, 256>>>(W2, W2_r, FF * DD / 4);
    tf32_round_strided<<<dim3(1, 1024), 256>>>(Wu + 2048, WuV_r, A3);
    tf32_round_strided<<<dim3(1, 1024), 256>>>(Wv + 2048, WvV_r, A3);

    // QKV-QK at 3xTF32 via PREC=2 pipeline; epilogue also emits K-cols hi/lo
    mma_gemm<128, 2><<<dim3(16, 16, 1), 256, S128_2>>>(
        src_hi, src_lo, 1024, Z, Z, WuQK_hi, WuQK_lo, 2048, Z, Z, 0,
        qkv_u, 3072, Z, Z, kc_hi, kc_lo, 2,
        1024, bu, 0, 1.f, INUL, 0);
    mma_gemm<128, 2><<<dim3(16, 16, 1), 256, S128_2>>>(
        aux_hi, aux_lo, 1024, Z, Z, WvQK_hi, WvQK_lo, 2048, Z, Z, 0,
        qkv_v, 3072, Z, Z, kc_hi + (size_t)BT * 1024, kc_lo + (size_t)BT * 1024, 2,
        1024, bv, 0, 1.f, INUL, 0);

    // QKV-V at tf32 (inputs pre-rounded: src_hi IS tf32(src))
    mma_gemm<128, 1><<<dim3(8, 16, 1), 256, S128_1>>>(
        src_hi, FNUL, 1024, Z, Z, WuV_r, FNUL, 1024, Z, Z, 0,
        qkv_u + 2048, 3072, Z, Z, MNUL, MNUL, 0,
        1024, bu + 2048, 0, 1.f, INUL, 1);
    mma_gemm<128, 1><<<dim3(8, 16, 1), 256, S128_1>>>(
        aux_hi, FNUL, 1024, Z, Z, WvV_r, FNUL, 1024, Z, Z, 0,
        qkv_v + 2048, 3072, Z, Z, MNUL, MNUL, 0,
        1024, bv + 2048, 0, 1.f, INUL, 1);

    // G = K_v^T diag(aux_mask) Q_v ; H = K_u^T diag(src_mask) Q_u
    gmat_part<<<dim3(32, 8), 256>>>(qkv_v, aux_mask, Gpart);
    gmat_reduce<<<dim3(32, 8), 256>>>(Gpart, Gb);
    gmat_part<<<dim3(32, 8), 256>>>(qkv_u, src_mask, Gpart);
    gmat_reduce<<<dim3(32, 8), 256>>>(Gpart, Hb);

    for (int s = 0; s < 2; s++) {
        const float* x   = (s == 0) ? src : aux;
        const float* qkv = (s == 0) ? qkv_u : qkv_v;
        const float* GH  = (s == 0) ? Gb : Hb;
        const int* mk    = (s == 0) ? src_mask : aux_mask;
        float* kch = kc_hi + (size_t)s * BT * 1024;
        float* kcl = kc_lo + (size_t)s * BT * 1024;
        float* outp = (float*)d_out + (size_t)s * BT * DD;

        // Q' = Q @ G (3xTF32, batched); epilogue emits qp hi/lo
        mma_gemm<64, 3><<<dim3(1, 8, 32), 256, S64_3>>>(
            qkv, FNUL, A3, (long long)TT * A3, 64,
            GH, FNUL, 64, (long long)16 * 4096, 4096, 0,
            qp, DD, (long long)TT * DD, 64, qp_hi, qp_lo, 1,
            64, FNUL, 0, 1.f, INUL, 0);

        // comb = (Q' K^T)/64 masked  (3xTF32 via PREC=2 pipeline, A*B^T)
        mma_gemm<128, 2><<<dim3(8, 8, 32), 256, S128_2>>>(
            qp_hi, qp_lo, DD, (long long)TT * DD, 64,
            kch, kcl, 1024, (long long)TT * 1024, 64, 1,
            comb, TT, (long long)16 * TT * TT, (long long)TT * TT, MNUL, MNUL, 0,
            64, FNUL, 0, inv64, mk, 0);

        softmax_kernel<<<32768, 256>>>(comb);

        // attn = att @ V (tf32; operands pre-rounded)
        mma_gemm<64, 1><<<dim3(1, 8, 32), 256, S64_1>>>(
            comb, FNUL, TT, (long long)16 * TT * TT, (long long)TT * TT,
            qkv + 2048, FNUL, A3, (long long)TT * A3, 64, 0,
            attn, DD, (long long)TT * DD, 64, MNUL, MNUL, 0,
            TT, FNUL, 0, 1.f, INUL, 1);

        // output projection + LN + FFN + LN (tf32)
        mma_gemm<128, 1><<<dim3(8, 16, 1), 256, S128_1>>>(
            attn, FNUL, 1024, Z, Z, Wo_r, FNUL, 1024, Z, Z, 0,
            proj, 1024, Z, Z, MNUL, MNUL, 0,
            1024, bo, 0, 1.f, INUL, 0);
        add_ln_kernel<<<2048, 256>>>(x, proj, g1, be1, o1, 1);
        mma_gemm<128, 1><<<dim3(32, 16, 1), 256, S128_1>>>(
            o1, FNUL, 1024, Z, Z, W1_r, FNUL, 4096, Z, Z, 0,
            ffn, 4096, Z, Z, MNUL, MNUL, 0,
            1024, b1, 1, 1.f, INUL, 1);
        mma_gemm<128, 1><<<dim3(8, 16, 1), 256, S128_1>>>(
            ffn, FNUL, 4096, Z, Z, W2_r, FNUL, 1024, Z, Z, 0,
            f2, 1024, Z, Z, MNUL, MNUL, 0,
            4096, b2, 0, 1.f, INUL, 0);
        add_ln_kernel<<<2048, 256>>>(o1, f2, g2, be2, outp, 0);
    }
}

// round 17
// speedup vs baseline: 1.0371x; 1.0371x over previous
#include <cuda_runtime.h>
#include <cstdint>

#define TT 1024      // timesteps
#define DD 1024      // model dim
#define A3 3072      // 3 * attention_dim
#define FF 4096      // feedforward dim
#define BT 2048      // B * T rows
#define NBH 32       // B * H batched heads

// ---------------- scratch (device globals; no allocations allowed) ----------------
__device__ float g_qkv_u[BT * A3];
__device__ float g_qkv_v[BT * A3];
__device__ float g_G[NBH * 4096];
__device__ float g_H[NBH * 4096];
__device__ float g_Gpart[8 * NBH * 4096];
__device__ float g_qp[BT * DD];
__device__ float g_comb[(size_t)NBH * TT * TT];
__device__ float g_attn[BT * DD];
__device__ float g_proj[BT * DD];
__device__ float g_o1[BT * DD];
__device__ float g_ffn[BT * FF];
__device__ float g_f2[BT * DD];
// tf32-rounded copies (producer-side rounding for tf32 GEMM operands)
__device__ float g_Wo_r[DD * DD];
__device__ float g_W1_r[DD * FF];
__device__ float g_W2_r[FF * DD];
__device__ float g_WuV_r[DD * DD];
__device__ float g_WvV_r[DD * DD];
__device__ float g_src_r[BT * DD];
__device__ float g_aux_r[BT * DD];

// xor-swizzled smem offset: row k (16 rows), m within row of width W.
#define SWZ(k, m, W) (((k) * (W)) + ((m) ^ (((((k) & 3) ^ (((k) >> 2) & 3))) << 3)))

__device__ __forceinline__ float f2tf32f(float x) {
    unsigned r;
    asm("cvt.rna.tf32.f32 %0, %1;" : "=r"(r) : "f"(x));
    return __uint_as_float(r);
}

#define MMA_TF32(d, a, b)                                                      \
    asm volatile(                                                              \
        "mma.sync.aligned.m16n8k8.row.col.f32.tf32.tf32.f32 "                  \
        "{%0,%1,%2,%3},{%4,%5,%6,%7},{%8,%9},{%0,%1,%2,%3};"                   \
        : "+f"((d)[0]), "+f"((d)[1]), "+f"((d)[2]), "+f"((d)[3])               \
        : "r"((a)[0]), "r"((a)[1]), "r"((a)[2]), "r"((a)[3]),                  \
          "r"((b)[0]), "r"((b)[1]))

#define CP_ASYNC16(dst, src)                                                   \
    asm volatile("cp.async.cg.shared.global [%0], [%1], 16;" :: "r"(dst), "l"(src))
#define CP_COMMIT() asm volatile("cp.async.commit_group;")
#define CP_WAIT(n)  asm volatile("cp.async.wait_group %0;" :: "n"(n))

// ---------------------------------------------------------------------------------
// PREC=1 GEMM: tf32 via cp.async 3-stage pipeline, 2 CTAs/SM.
// All operands are pre-rounded to tf32-representable fp32 by their producers,
// so the MMA's internal truncation is exact.
// Pipeline invariant: slab s lives in stage (s % STAGES). Prologue fills
// slabs 0..STAGES-2; iteration s consumes stage s%STAGES and refills slab
// s+STAGES-1 into stage (s+STAGES-1)%STAGES (= the stage consumed at s-1,
// whose readers are all past this iteration's __syncthreads).
// ---------------------------------------------------------------------------------
template <int BN>
__global__ void __launch_bounds__(256, 2) mma_gemm1(
    const float* __restrict__ A, int lda, long long sAb, long long sAh,
    const float* __restrict__ B, int ldb, long long sBb, long long sBh,
    float* __restrict__ C, int ldc, long long sCb, long long sCh,
    int K, const float* __restrict__ bias, int relu, float scale, int round_out)
{
    constexpr int NF = BN / 16;
    constexpr int BF4 = (BN * 16 / 4) / 256;
    constexpr int NH = (NF > 4) ? 2 : 1;
    constexpr int NFH = NF / NH;
    constexpr int STAGES = 3;
    constexpr int AW = 16 * 128;
    constexpr int BW = 16 * BN;

    extern __shared__ float sm[];
    float* Af = sm;
    float* Bf = sm + STAGES * AW;
    unsigned aBase = (unsigned)__cvta_generic_to_shared(Af);
    unsigned bBase = (unsigned)__cvta_generic_to_shared(Bf);

    int z = blockIdx.z, b = z >> 4, h = z & 15;
    A += (size_t)b * sAb + (size_t)h * sAh;
    B += (size_t)b * sBb + (size_t)h * sBh;
    C += (size_t)b * sCb + (size_t)h * sCh;

    int tid = threadIdx.x, lane = tid & 31, warp = tid >> 5;
    int wy = warp >> 1, wx = warp & 1;
    int wm = wy * 32, wn = wx * (BN / 2);
    int g = lane >> 2, q = lane & 3;
    int m0 = blockIdx.y * 128, n0 = blockIdx.x * BN;

    float acc[2][NF][4];
    #pragma unroll
    for (int mi = 0; mi < 2; mi++)
        #pragma unroll
        for (int nj = 0; nj < NF; nj++)
            #pragma unroll
            for (int e = 0; e < 4; e++) acc[mi][nj][e] = 0.f;

    auto issue = [&](int slab, int stg) {
        #pragma unroll
        for (int i = 0; i < 2; i++) {
            int id = tid + 256 * i;
            int m = id >> 2, c = id & 3;
            const float* src = A + (size_t)(m0 + m) * lda + slab * 16 + c * 4;
            unsigned dst = aBase + (unsigned)(stg * AW + m * 16 + ((c ^ (m & 3)) << 2)) * 4u;
            CP_ASYNC16(dst, src);
        }
        #pragma unroll
        for (int i = 0; i < BF4; i++) {
            int id = tid + 256 * i;
            int kr = id / (BN / 4), nc4 = (id % (BN / 4)) * 4;
            const float* src = B + (size_t)(slab * 16 + kr) * ldb + n0 + nc4;
            int sw = (((kr & 3) ^ ((kr >> 2) & 3)) << 3);
            unsigned dst = bBase + (unsigned)(stg * BW + kr * BN + (nc4 ^ sw)) * 4u;
            CP_ASYNC16(dst, src);
        }
        CP_COMMIT();
    };

    int nslab = K / 16;
    #pragma unroll
    for (int s = 0; s < STAGES - 1; s++) issue(s, s);

    int cstg = 0, fstg = STAGES - 1;   // consume stage = s % STAGES; fill stage = (s+STAGES-1) % STAGES
    for (int s = 0; s < nslab; s++) {
        CP_WAIT(STAGES - 2);
        __syncthreads();
        const float* pa = Af + cstg * AW;
        const float* pb = Bf + cstg * BW;

        #pragma unroll
        for (int kk = 0; kk < 16; kk += 8) {
            unsigned ah[2][4];
            #pragma unroll
            for (int mi = 0; mi < 2; mi++)
                #pragma unroll
                for (int e = 0; e < 4; e++) {
                    int m = wm + mi * 16 + g + ((e & 1) ? 8 : 0);
                    int c = (kk >> 2) + ((e >= 2) ? 1 : 0);
                    ah[mi][e] = __float_as_uint(pa[m * 16 + q + ((c ^ (m & 3)) << 2)]);
                }
            #pragma unroll
            for (int hh = 0; hh < NH; hh++) {
                unsigned bh[NFH][2];
                #pragma unroll
                for (int j = 0; j < NFH; j++) {
                    int n = wn + (hh * NFH + j) * 8 + g;
                    bh[j][0] = __float_as_uint(pb[SWZ(kk + q, n, BN)]);
                    bh[j][1] = __float_as_uint(pb[SWZ(kk + q + 4, n, BN)]);
                }
                #pragma unroll
                for (int mi = 0; mi < 2; mi++)
                    #pragma unroll
                    for (int j = 0; j < NFH; j++)
                        MMA_TF32(acc[mi][hh * NFH + j], ah[mi], bh[j]);
            }
        }

        int nxt = s + STAGES - 1;
        if (nxt < nslab) issue(nxt, fstg);
        else CP_COMMIT();
        cstg = (cstg + 1 == STAGES) ? 0 : cstg + 1;
        fstg = (fstg + 1 == STAGES) ? 0 : fstg + 1;
    }

    #pragma unroll
    for (int mi = 0; mi < 2; mi++)
        #pragma unroll
        for (int r2 = 0; r2 < 2; r2++) {
            int row = m0 + wm + mi * 16 + g + r2 * 8;
            #pragma unroll
            for (int nj = 0; nj < NF; nj++) {
                int col = n0 + wn + nj * 8 + 2 * q;
                float v0 = acc[mi][nj][r2 * 2 + 0] * scale;
                float v1 = acc[mi][nj][r2 * 2 + 1] * scale;
                if (bias) { v0 += bias[col]; v1 += bias[col + 1]; }
                if (relu) { v0 = fmaxf(v0, 0.f); v1 = fmaxf(v1, 0.f); }
                if (round_out) { v0 = f2tf32f(v0); v1 = f2tf32f(v1); }
                float2 o; o.x = v0; o.y = v1;
                *(float2*)&C[(size_t)row * ldc + col] = o;
            }
        }
}

// ---------------------------------------------------------------------------------
// PREC=3 GEMM: 3xTF32, cvt-at-store hi/lo double buffer (round-14 winner, verbatim)
// ---------------------------------------------------------------------------------
template <int BN>
__global__ void __launch_bounds__(256) mma_gemm3(
    const float* __restrict__ A, int lda, long long sAb, long long sAh,
    const float* __restrict__ B, int ldb, long long sBb, long long sBh, int transB,
    float* __restrict__ C, int ldc, long long sCb, long long sCh,
    int K, const float* __restrict__ bias, float scale,
    const int* __restrict__ mask)
{
    constexpr int NF = BN / 16;
    constexpr int BF4 = (BN * 16 / 4) / 256;
    constexpr int NH = (NF > 4) ? 2 : 1;
    constexpr int NFH = NF / NH;
    constexpr int CC = 2;
    constexpr int AE = 16 * 128;
    constexpr int BE = 16 * BN;

    extern __shared__ float sm[];
    float* Asm = sm;
    float* Bsm = sm + 2 * CC * AE;

    int z = blockIdx.z, b = z >> 4, h = z & 15;
    A += (size_t)b * sAb + (size_t)h * sAh;
    B += (size_t)b * sBb + (size_t)h * sBh;
    C += (size_t)b * sCb + (size_t)h * sCh;
    const int* mrow = mask ? (mask + b * TT) : (const int*)0;

    int tid = threadIdx.x, lane = tid & 31, warp = tid >> 5;
    int wy = warp >> 1, wx = warp & 1;
    int wm = wy * 32, wn = wx * (BN / 2);
    int g = lane >> 2, q = lane & 3;
    int m0 = blockIdx.y * 128, n0 = blockIdx.x * BN;

    float acc[2][NF][4];
    #pragma unroll
    for (int mi = 0; mi < 2; mi++)
        #pragma unroll
        for (int nj = 0; nj < NF; nj++)
            #pragma unroll
            for (int e = 0; e < 4; e++) acc[mi][nj][e] = 0.f;

    float4 va[2];
    float4 vb[BF4];

    auto loadA = [&](int k0) {
        #pragma unroll
        for (int i = 0; i < 2; i++) {
            int id = tid + 256 * i;
            int r = id >> 2, c4 = (id & 3) * 4;
            va[i] = *(const float4*)&A[(size_t)(m0 + r) * lda + k0 + c4];
        }
    };
    auto storeA = [&](int bf) {
        float* p = Asm + bf * CC * AE;
        #pragma unroll
        for (int i = 0; i < 2; i++) {
            int id = tid + 256 * i;
            int r = id >> 2, c4 = (id & 3) * 4;
            float xs[4] = {va[i].x, va[i].y, va[i].z, va[i].w};
            #pragma unroll
            for (int s = 0; s < 4; s++) {
                float hi = f2tf32f(xs[s]);
                p[SWZ(c4 + s, r, 128)] = hi;
                p[AE + SWZ(c4 + s, r, 128)] = f2tf32f(xs[s] - hi);
            }
        }
    };
    auto loadB = [&](int k0) {
        if (!transB) {
            #pragma unroll
            for (int i = 0; i < BF4; i++) {
                int id = tid + 256 * i;
                int kr = id / (BN / 4), nc4 = (id % (BN / 4)) * 4;
                vb[i] = *(const float4*)&B[(size_t)(k0 + kr) * ldb + n0 + nc4];
            }
        } else {
            #pragma unroll
            for (int i = 0; i < BF4; i++) {
                int id = tid + 256 * i;
                int n = id >> 2, c4 = (id & 3) * 4;
                vb[i] = *(const float4*)&B[(size_t)(n0 + n) * ldb + k0 + c4];
            }
        }
    };
    auto storeB = [&](int bf) {
        float* p = Bsm + bf * CC * BE;
        if (!transB) {
            #pragma unroll
            for (int i = 0; i < BF4; i++) {
                int id = tid + 256 * i;
                int kr = id / (BN / 4), nc4 = (id % (BN / 4)) * 4;
                int sw = (((kr & 3) ^ ((kr >> 2) & 3)) << 3);
                float xs[4] = {vb[i].x, vb[i].y, vb[i].z, vb[i].w};
                float4 hv, lv;
                hv.x = f2tf32f(xs[0]); hv.y = f2tf32f(xs[1]);
                hv.z = f2tf32f(xs[2]); hv.w = f2tf32f(xs[3]);
                *(float4*)&p[kr * BN + (nc4 ^ sw)] = hv;
                lv.x = f2tf32f(xs[0] - hv.x); lv.y = f2tf32f(xs[1] - hv.y);
                lv.z = f2tf32f(xs[2] - hv.z); lv.w = f2tf32f(xs[3] - hv.w);
                *(float4*)&p[BE + kr * BN + (nc4 ^ sw)] = lv;
            }
        } else {
            #pragma unroll
            for (int i = 0; i < BF4; i++) {
                int id = tid + 256 * i;
                int n = id >> 2, c4 = (id & 3) * 4;
                float xs[4] = {vb[i].x, vb[i].y, vb[i].z, vb[i].w};
                #pragma unroll
                for (int s = 0; s < 4; s++) {
                    float hi = f2tf32f(xs[s]);
                    p[SWZ(c4 + s, n, BN)] = hi;
                    p[BE + SWZ(c4 + s, n, BN)] = f2tf32f(xs[s] - hi);
                }
            }
        }
    };

    loadA(0); loadB(0);
    storeA(0); storeB(0);
    __syncthreads();

    int buf = 0;
    for (int k0 = 0; k0 < K; k0 += 16) {
        bool more = (k0 + 16) < K;
        if (more) { loadA(k0 + 16); loadB(k0 + 16); }

        const float* pa = Asm + buf * CC * AE;
        const float* pb = Bsm + buf * CC * BE;

        #pragma unroll
        for (int kk = 0; kk < 16; kk += 8) {
            unsigned ah[2][4], al[2][4];
            #pragma unroll
            for (int mi = 0; mi < 2; mi++)
                #pragma unroll
                for (int e = 0; e < 4; e++) {
                    int kq = kk + q + ((e >= 2) ? 4 : 0);
                    int m = wm + mi * 16 + g + ((e & 1) ? 8 : 0);
                    ah[mi][e] = __float_as_uint(pa[SWZ(kq, m, 128)]);
                    al[mi][e] = __float_as_uint(pa[AE + SWZ(kq, m, 128)]);
                }
            #pragma unroll
            for (int hh = 0; hh < NH; hh++) {
                unsigned bh[NFH][2], bl[NFH][2];
                #pragma unroll
                for (int j = 0; j < NFH; j++) {
                    int n = wn + (hh * NFH + j) * 8 + g;
                    bh[j][0] = __float_as_uint(pb[SWZ(kk + q, n, BN)]);
                    bh[j][1] = __float_as_uint(pb[SWZ(kk + q + 4, n, BN)]);
                    bl[j][0] = __float_as_uint(pb[BE + SWZ(kk + q, n, BN)]);
                    bl[j][1] = __float_as_uint(pb[BE + SWZ(kk + q + 4, n, BN)]);
                }
                #pragma unroll
                for (int mi = 0; mi < 2; mi++)
                    #pragma unroll
                    for (int j = 0; j < NFH; j++) {
                        int nj = hh * NFH + j;
                        MMA_TF32(acc[mi][nj], ah[mi], bh[j]);
                        MMA_TF32(acc[mi][nj], ah[mi], bl[j]);
                        MMA_TF32(acc[mi][nj], al[mi], bh[j]);
                    }
            }
        }

        if (more) {
            storeA(buf ^ 1); storeB(buf ^ 1);
            buf ^= 1;
            __syncthreads();
        }
    }

    #pragma unroll
    for (int mi = 0; mi < 2; mi++)
        #pragma unroll
        for (int r2 = 0; r2 < 2; r2++) {
            int row = m0 + wm + mi * 16 + g + r2 * 8;
            #pragma unroll
            for (int nj = 0; nj < NF; nj++) {
                int col = n0 + wn + nj * 8 + 2 * q;
                float v0 = acc[mi][nj][r2 * 2 + 0] * scale;
                float v1 = acc[mi][nj][r2 * 2 + 1] * scale;
                if (bias) { v0 += bias[col]; v1 += bias[col + 1]; }
                if (mrow) {
                    if (!mrow[col]) v0 = 0.f;
                    if (!mrow[col + 1]) v1 = 0.f;
                }
                float2 o; o.x = v0; o.y = v1;
                *(float2*)&C[(size_t)row * ldc + col] = o;
            }
        }
}

// -------- producer-side tf32 round kernels ----------------------------------------
__global__ void __launch_bounds__(256) tf32_round_kernel(
    const float* __restrict__ in, float* __restrict__ out, int n4)
{
    int i = blockIdx.x * 256 + threadIdx.x;
    if (i < n4) {
        float4 v = ((const float4*)in)[i];
        v.x = f2tf32f(v.x); v.y = f2tf32f(v.y); v.z = f2tf32f(v.z); v.w = f2tf32f(v.w);
        ((float4*)out)[i] = v;
    }
}

__global__ void __launch_bounds__(256) tf32_round_strided(
    const float* __restrict__ in, float* __restrict__ out, int ld_in)
{
    int r = blockIdx.y;
    int c = threadIdx.x * 4;
    float4 v = *(const float4*)(in + (size_t)r * ld_in + c);
    v.x = f2tf32f(v.x); v.y = f2tf32f(v.y); v.z = f2tf32f(v.z); v.w = f2tf32f(v.w);
    *(float4*)(out + (size_t)r * 1024 + c) = v;
}

// -------- split-K G partials: G = K^T diag(mask) Q per (b,h). grid (32, 8) -------
__global__ void __launch_bounds__(256) gmat_part(
    const float* __restrict__ qkv, const int* __restrict__ mask, float* __restrict__ part)
{
    int z = blockIdx.x; int b = z >> 4; int h = z & 15;
    int tb = blockIdx.y * 128;
    const float* Kb = qkv + (size_t)b * TT * A3 + 1024 + h * 64;
    const float* Qb = qkv + (size_t)b * TT * A3 + h * 64;
    __shared__ float Ks[64][65];
    __shared__ float Qs[64][65];
    int tid = threadIdx.x, tx = tid & 15, ty = tid >> 4;
    float acc[4][4] = {};

    for (int t0 = tb; t0 < tb + 128; t0 += 64) {
        #pragma unroll
        for (int l = 0; l < 4; l++) {
            int lin = tid + l * 256; int r = lin >> 4; int c4 = (lin & 15) * 4;
            int trow = t0 + r;
            float mk = mask[b * TT + trow] ? 1.0f : 0.0f;
            float4 kv = *(const float4*)&Kb[(size_t)trow * A3 + c4];
            Ks[r][c4] = kv.x * mk; Ks[r][c4 + 1] = kv.y * mk;
            Ks[r][c4 + 2] = kv.z * mk; Ks[r][c4 + 3] = kv.w * mk;
            float4 qv = *(const float4*)&Qb[(size_t)trow * A3 + c4];
            Qs[r][c4] = qv.x; Qs[r][c4 + 1] = qv.y; Qs[r][c4 + 2] = qv.z; Qs[r][c4 + 3] = qv.w;
        }
        __syncthreads();
        #pragma unroll
        for (int t = 0; t < 64; t++) {
            float ra[4], rb[4];
            #pragma unroll
            for (int i = 0; i < 4; i++) ra[i] = Ks[t][ty * 4 + i];
            #pragma unroll
            for (int j = 0; j < 4; j++) rb[j] = Qs[t][tx * 4 + j];
            #pragma unroll
            for (int i = 0; i < 4; i++)
                #pragma unroll
                for (int j = 0; j < 4; j++) acc[i][j] = fmaf(ra[i], rb[j], acc[i][j]);
        }
        __syncthreads();
    }
    float* P = part + ((size_t)blockIdx.y * NBH + z) * 4096;
    #pragma unroll
    for (int i = 0; i < 4; i++) {
        float4 o; o.x = acc[i][0]; o.y = acc[i][1]; o.z = acc[i][2]; o.w = acc[i][3];
        *(float4*)&P[(ty * 4 + i) * 64 + tx * 4] = o;
    }
}

__global__ void __launch_bounds__(256) gmat_reduce(
    const float* __restrict__ part, float* __restrict__ G)
{
    int z = blockIdx.x;
    int e = blockIdx.y * 512 + threadIdx.x;
    #pragma unroll
    for (int i = 0; i < 2; i++, e += 256) {
        float s = 0.f;
        #pragma unroll
        for (int k = 0; k < 8; k++) s += part[((size_t)k * NBH + z) * 4096 + e];
        G[(size_t)z * 4096 + e] = s;
    }
}

// -------- row softmax over 1024 cols, in place; output tf32-rounded --------------
__global__ void __launch_bounds__(256) softmax_kernel(float* __restrict__ data)
{
    __shared__ float red[8];
    size_t row = blockIdx.x;
    float4* p = (float4*)(data + row * TT);
    int tid = threadIdx.x;
    float4 v = p[tid];
    float m = fmaxf(fmaxf(v.x, v.y), fmaxf(v.z, v.w));
    #pragma unroll
    for (int o = 16; o; o >>= 1) m = fmaxf(m, __shfl_xor_sync(0xffffffffu, m, o));
    if ((tid & 31) == 0) red[tid >> 5] = m;
    __syncthreads();
    m = red[0];
    #pragma unroll
    for (int i = 1; i < 8; i++) m = fmaxf(m, red[i]);
    v.x = expf(v.x - m); v.y = expf(v.y - m); v.z = expf(v.z - m); v.w = expf(v.w - m);
    float s = v.x + v.y + v.z + v.w;
    #pragma unroll
    for (int o = 16; o; o >>= 1) s += __shfl_xor_sync(0xffffffffu, s, o);
    __syncthreads();
    if ((tid & 31) == 0) red[tid >> 5] = s;
    __syncthreads();
    s = red[0] + red[1] + red[2] + red[3] + red[4] + red[5] + red[6] + red[7];
    float inv = 1.0f / s;
    v.x = f2tf32f(v.x * inv); v.y = f2tf32f(v.y * inv);
    v.z = f2tf32f(v.z * inv); v.w = f2tf32f(v.w * inv);
    p[tid] = v;
}

// -------- out = LayerNorm(x + y) * g + b (optionally tf32-rounded) ---------------
__global__ void __launch_bounds__(256) add_ln_kernel(
    const float* __restrict__ x, const float* __restrict__ y,
    const float* __restrict__ g, const float* __restrict__ beta,
    float* __restrict__ out, int round_out)
{
    __shared__ float s1[8], s2[8];
    size_t row = blockIdx.x;
    int tid = threadIdx.x;
    float4 xv = ((const float4*)(x + row * DD))[tid];
    float4 yv = ((const float4*)(y + row * DD))[tid];
    float4 v;
    v.x = xv.x + yv.x; v.y = xv.y + yv.y; v.z = xv.z + yv.z; v.w = xv.w + yv.w;
    float s = v.x + v.y + v.z + v.w;
    float q = v.x * v.x + v.y * v.y + v.z * v.z + v.w * v.w;
    #pragma unroll
    for (int o = 16; o; o >>= 1) {
        s += __shfl_xor_sync(0xffffffffu, s, o);
        q += __shfl_xor_sync(0xffffffffu, q, o);
    }
    if ((tid & 31) == 0) { s1[tid >> 5] = s; s2[tid >> 5] = q; }
    __syncthreads();
    s = s1[0] + s1[1] + s1[2] + s1[3] + s1[4] + s1[5] + s1[6] + s1[7];
    q = s2[0] + s2[1] + s2[2] + s2[3] + s2[4] + s2[5] + s2[6] + s2[7];
    float mean = s * (1.0f / 1024.0f);
    float var = q * (1.0f / 1024.0f) - mean * mean;
    float r = rsqrtf(var + 1e-5f);
    float4 gv = ((const float4*)g)[tid];
    float4 bv = ((const float4*)beta)[tid];
    float4 o;
    o.x = (v.x - mean) * r * gv.x + bv.x;
    o.y = (v.y - mean) * r * gv.y + bv.y;
    o.z = (v.z - mean) * r * gv.z + bv.z;
    o.w = (v.w - mean) * r * gv.w + bv.w;
    if (round_out) {
        o.x = f2tf32f(o.x); o.y = f2tf32f(o.y);
        o.z = f2tf32f(o.z); o.w = f2tf32f(o.w);
    }
    ((float4*)(out + row * DD))[tid] = o;
}

// ----------------------------------- host ----------------------------------------
static inline int smem1_bytes(int BN) { return 3 * (16 * 128 + 16 * BN) * 4; }
static inline int smem3_bytes(int BN) { return (2 * 2 * 16 * 128 + 2 * 2 * 16 * BN) * 4; }

extern "C" void kernel_launch(void* const* d_in, const int* in_sizes, int n_in,
                              void* d_out, int out_size)
{
    const float* src = (const float*)d_in[0];
    const float* aux = (const float*)d_in[1];
    const float* Wu  = (const float*)d_in[2];
    const float* bu  = (const float*)d_in[3];
    const float* Wv  = (const float*)d_in[4];
    const float* bv  = (const float*)d_in[5];
    const float* Wo  = (const float*)d_in[6];
    const float* bo  = (const float*)d_in[7];
    const float* W1  = (const float*)d_in[8];
    const float* b1  = (const float*)d_in[9];
    const float* W2  = (const float*)d_in[10];
    const float* b2  = (const float*)d_in[11];
    const float* g1  = (const float*)d_in[12];
    const float* be1 = (const float*)d_in[13];
    const float* g2  = (const float*)d_in[14];
    const float* be2 = (const float*)d_in[15];
    const int* src_mask = (const int*)d_in[16];
    const int* aux_mask = (const int*)d_in[17];

    float *qkv_u, *qkv_v, *Gb, *Hb, *Gpart, *qp, *comb, *attn, *proj, *o1, *ffn, *f2;
    float *Wo_r, *W1_r, *W2_r, *WuV_r, *WvV_r, *src_r, *aux_r;
    cudaGetSymbolAddress((void**)&qkv_u, g_qkv_u);
    cudaGetSymbolAddress((void**)&qkv_v, g_qkv_v);
    cudaGetSymbolAddress((void**)&Gb, g_G);
    cudaGetSymbolAddress((void**)&Hb, g_H);
    cudaGetSymbolAddress((void**)&Gpart, g_Gpart);
    cudaGetSymbolAddress((void**)&qp, g_qp);
    cudaGetSymbolAddress((void**)&comb, g_comb);
    cudaGetSymbolAddress((void**)&attn, g_attn);
    cudaGetSymbolAddress((void**)&proj, g_proj);
    cudaGetSymbolAddress((void**)&o1, g_o1);
    cudaGetSymbolAddress((void**)&ffn, g_ffn);
    cudaGetSymbolAddress((void**)&f2, g_f2);
    cudaGetSymbolAddress((void**)&Wo_r, g_Wo_r);
    cudaGetSymbolAddress((void**)&W1_r, g_W1_r);
    cudaGetSymbolAddress((void**)&W2_r, g_W2_r);
    cudaGetSymbolAddress((void**)&WuV_r, g_WuV_r);
    cudaGetSymbolAddress((void**)&WvV_r, g_WvV_r);
    cudaGetSymbolAddress((void**)&src_r, g_src_r);
    cudaGetSymbolAddress((void**)&aux_r, g_aux_r);

    // raise dynamic-smem caps — unconditional (idempotent host-side config)
    cudaFuncSetAttribute(mma_gemm1<128>, cudaFuncAttributeMaxDynamicSharedMemorySize, smem1_bytes(128));
    cudaFuncSetAttribute(mma_gemm1<64>,  cudaFuncAttributeMaxDynamicSharedMemorySize, smem1_bytes(64));
    cudaFuncSetAttribute(mma_gemm3<128>, cudaFuncAttributeMaxDynamicSharedMemorySize, smem3_bytes(128));
    cudaFuncSetAttribute(mma_gemm3<64>,  cudaFuncAttributeMaxDynamicSharedMemorySize, smem3_bytes(64));

    const float inv64 = 1.0f / 64.0f;
    const long long Z = 0;
    const int S128_1 = smem1_bytes(128), S64_1 = smem1_bytes(64);
    const int S128_3 = smem3_bytes(128), S64_3 = smem3_bytes(64);
    const float* FNUL = (const float*)0;
    const int* INUL = (const int*)0;

    // producer-side tf32 rounding of PREC=1 operands (weights + raw inputs)
    tf32_round_kernel<<<(DD * DD / 4 + 255) / 256, 256>>>(Wo, Wo_r, DD * DD / 4);
    tf32_round_kernel<<<(DD * FF / 4 + 255) / 256, 256>>>(W1, W1_r, DD * FF / 4);
    tf32_round_kernel<<<(FF * DD / 4 + 255) / 256, 256>>>(W2, W2_r, FF * DD / 4);
    tf32_round_kernel<<<(BT * DD / 4 + 255) / 256, 256>>>(src, src_r, BT * DD / 4);
    tf32_round_kernel<<<(BT * DD / 4 + 255) / 256, 256>>>(aux, aux_r, BT * DD / 4);
    tf32_round_strided<<<dim3(1, 1024), 256>>>(Wu + 2048, WuV_r, A3);
    tf32_round_strided<<<dim3(1, 1024), 256>>>(Wv + 2048, WvV_r, A3);

    // dual-stream QKV projections: Q,K columns at 3xTF32 (logit chain), V at tf32
    mma_gemm3<128><<<dim3(16, 16, 1), 256, S128_3>>>(src, 1024, Z, Z, Wu, 3072, Z, Z, 0,
                                                     qkv_u, 3072, Z, Z, 1024, bu, 1.f, INUL);
    mma_gemm1<128><<<dim3(8, 16, 1), 256, S128_1>>>(src_r, 1024, Z, Z, WuV_r, 1024, Z, Z,
                                                    qkv_u + 2048, 3072, Z, Z, 1024, bu + 2048, 0, 1.f, 1);
    mma_gemm3<128><<<dim3(16, 16, 1), 256, S128_3>>>(aux, 1024, Z, Z, Wv, 3072, Z, Z, 0,
                                                     qkv_v, 3072, Z, Z, 1024, bv, 1.f, INUL);
    mma_gemm1<128><<<dim3(8, 16, 1), 256, S128_1>>>(aux_r, 1024, Z, Z, WvV_r, 1024, Z, Z,
                                                    qkv_v + 2048, 3072, Z, Z, 1024, bv + 2048, 0, 1.f, 1);

    // G = K_v^T diag(aux_mask) Q_v ; H = K_u^T diag(src_mask) Q_u  (split-K + reduce)
    gmat_part<<<dim3(32, 8), 256>>>(qkv_v, aux_mask, Gpart);
    gmat_reduce<<<dim3(32, 8), 256>>>(Gpart, Gb);
    gmat_part<<<dim3(32, 8), 256>>>(qkv_u, src_mask, Gpart);
    gmat_reduce<<<dim3(32, 8), 256>>>(Gpart, Hb);

    for (int s = 0; s < 2; s++) {
        const float* x   = (s == 0) ? src : aux;
        const float* qkv = (s == 0) ? qkv_u : qkv_v;
        const float* GH  = (s == 0) ? Gb : Hb;
        const int* mk    = (s == 0) ? src_mask : aux_mask;
        float* outp = (float*)d_out + (size_t)s * BT * DD;

        // Q' = Q @ G   (3xTF32, batched per head, N=64)
        mma_gemm3<64><<<dim3(1, 8, 32), 256, S64_3>>>(
            qkv, A3, (long long)TT * A3, 64,
            GH, 64, (long long)16 * 4096, 4096, 0,
            qp, DD, (long long)TT * DD, 64,
            64, FNUL, 1.f, INUL);

        // comb = (Q' K^T)/64, masked key cols -> 0  (3xTF32, A*B^T)
        mma_gemm3<128><<<dim3(8, 8, 32), 256, S128_3>>>(
            qp, DD, (long long)TT * DD, 64,
            qkv + 1024, A3, (long long)TT * A3, 64, 1,
            comb, TT, (long long)16 * TT * TT, (long long)TT * TT,
            64, FNUL, inv64, mk);

        softmax_kernel<<<32768, 256>>>(comb);

        // attn = att @ V  (tf32; operands pre-rounded)
        mma_gemm1<64><<<dim3(1, 8, 32), 256, S64_1>>>(
            comb, TT, (long long)16 * TT * TT, (long long)TT * TT,
            qkv + 2048, A3, (long long)TT * A3, 64,
            attn, DD, (long long)TT * DD, 64,
            TT, FNUL, 0, 1.f, 1);

        // output projection + LN + FFN + LN  (tf32, operands pre-rounded)
        mma_gemm1<128><<<dim3(8, 16, 1), 256, S128_1>>>(attn, 1024, Z, Z, Wo_r, 1024, Z, Z,
                                                        proj, 1024, Z, Z, 1024, bo, 0, 1.f, 0);
        add_ln_kernel<<<2048, 256>>>(x, proj, g1, be1, o1, 1);
        mma_gemm1<128><<<dim3(32, 16, 1), 256, S128_1>>>(o1, 1024, Z, Z, W1_r, 4096, Z, Z,
                                                         ffn, 4096, Z, Z, 1024, b1, 1, 1.f, 1);
        mma_gemm1<128><<<dim3(8, 16, 1), 256, S128_1>>>(ffn, 4096, Z, Z, W2_r, 1024, Z, Z,
                                                        f2, 1024, Z, Z, 4096, b2, 0, 1.f, 0);
        add_ln_kernel<<<2048, 256>>>(o1, f2, g2, be2, outp, 0);
    }
}